// round 16
// baseline (speedup 1.0000x reference)
#include <cuda_runtime.h>
#include <cstdint>

// out[b,i,j,c] = sum_k exp(-2(li-x0k)^2)*exp(-2(lj-x1k)^2)*Yb[k,c]
// GEMM: C[64 x 640] = A[64 x 1024] * Z[1024 x 640], bf16 mma m16n8k16.
// PDL: mma kernel launches overlapped with prep; grid-dep sync before phase 2.
#define NB    16
#define NN    1024
#define STEP  (6.0f / 63.0f)
#define EX2C  (-2.885390081777927f)   // -2*log2(e)

// A frags: u32 idx = b*32768 + kstep*512 + slab*128 + lane*4 + q
__device__ __align__(16) uint32_t g_Aperm[NB * 64 * 4 * 32 * 4];

__device__ __forceinline__ float ex2f(float x) {
    float r; asm("ex2.approx.ftz.f32 %0, %1;" : "=f"(r) : "f"(x)); return r;
}
__device__ __forceinline__ uint32_t pack_bf16(float lo, float hi) {
    uint32_t d;
    asm("cvt.rn.bf16x2.f32 %0, %1, %2;" : "=r"(d) : "f"(hi), "f"(lo));
    return d;
}
#define MMA_BF16(d, a, bb) \
    asm volatile("mma.sync.aligned.m16n8k16.row.col.f32.bf16.bf16.f32 " \
        "{%0,%1,%2,%3}, {%4,%5,%6,%7}, {%8,%9}, {%0,%1,%2,%3};" \
        : "+f"(d[0]), "+f"(d[1]), "+f"(d[2]), "+f"(d[3]) \
        : "r"(a.x), "r"(a.y), "r"(a.z), "r"(a.w), "r"(bb.x), "r"(bb.y))
#define GROUP_BAR(id) \
    asm volatile("bar.sync %0, 256;" :: "r"(id) : "memory")

// ---------- prep: A frags + grid coords (512 CTAs) ----------
__global__ __launch_bounds__(256)
void rkhs_prep_kernel(const float* __restrict__ X, float* __restrict__ out)
{
    int tid = blockIdx.x * blockDim.x + threadIdx.x;
    if (tid < 4096) {
        out[tid * 2 + 0] = -3.0f + (float)(tid >> 6) * STEP;
        out[tid * 2 + 1] = -3.0f + (float)(tid & 63) * STEP;
    }
    int q     = tid & 3;
    int lane  = (tid >> 2) & 31;
    int kstep = (tid >> 7) & 63;
    int b     = tid >> 13;

    int kb = kstep * 16 + ((lane & 3) << 1) + ((q >> 1) << 3);
    float4 xx = *(const float4*)(X + (size_t)(b * NN + kb) * 2);
    int rbase = (lane >> 2) + ((q & 1) << 3);
    uint32_t* dst = g_Aperm + (b * 32768 + kstep * 512 + lane * 4 + q);
#pragma unroll
    for (int slab = 0; slab < 4; ++slab) {
        float li = -3.0f + (float)(slab * 16 + rbase) * STEP;
        float d0 = li - xx.x;
        float d1 = li - xx.z;
        dst[slab * 128] = pack_bf16(ex2f(d0 * d0 * EX2C), ex2f(d1 * d1 * EX2C));
    }
}

// ---------- main: grid 256 = (b,jt), 512 thr = 2 K-groups ----------
#define ZSLOTS (64 * 5 * 32)      // 10240 uint2 = 81920 B

__global__ __launch_bounds__(512, 2)
void rkhs_mma_kernel(const float* __restrict__ X, const float* __restrict__ Y,
                     float* __restrict__ out)
{
    extern __shared__ __align__(16) uint2 sZ[];   // [kstep*5+nc][32]

    const int bx = blockIdx.x;
    const int jt = bx & 15;
    const int b  = bx >> 4;
    const int t  = threadIdx.x;

    const int ks = t >> 8;            // K-group 0/1
    const int tl = t & 255;

    // ===== Phase 1: build THIS group's Z half; 1 jl-pair item/thread =====
    // (does NOT read g_Aperm -> overlaps with prep under PDL)
    {
        const float* yb = Y + (size_t)b * (NN * 8);
        int jlp   = tl & 1;                 // jl pair: {2*jlp, 2*jlp+1}
        int q     = (tl >> 1) & 3;
        int kstep = ks * 32 + (tl >> 3);
        int klo   = kstep * 16 + q * 2;     // k's: klo, klo+1, klo+8, klo+9

        float4 xA = *(const float4*)(X + (size_t)(b * NN + klo) * 2);
        float4 xB = *(const float4*)(X + (size_t)(b * NN + klo + 8) * 2);

        const float4* y0p = (const float4*)(yb + (size_t)klo * 8);
        float4 y0a = y0p[0],  y0b = y0p[1];
        float4 y1a = y0p[2],  y1b = y0p[3];
        float4 y8a = y0p[16], y8b = y0p[17];
        float4 y9a = y0p[18], y9b = y0p[19];

        float Y0[8] = {y0a.x, y0a.y, y0a.z, y0a.w, y0b.x, y0b.y, y0b.z, y0b.w};
        float Y1[8] = {y1a.x, y1a.y, y1a.z, y1a.w, y1b.x, y1b.y, y1b.z, y1b.w};
        float Y8[8] = {y8a.x, y8a.y, y8a.z, y8a.w, y8b.x, y8b.y, y8b.z, y8b.w};
        float Y9[8] = {y9a.x, y9a.y, y9a.z, y9a.w, y9b.x, y9b.y, y9b.z, y9b.w};

        uint2* zk = sZ + (size_t)kstep * 5 * 32 + q;
#pragma unroll
        for (int jv = 0; jv < 2; ++jv) {
            int jl = jlp * 2 + jv;
            float lj = -3.0f + (float)(jt * 4 + jl) * STEP;
            float dA0 = lj - xA.y, dA1 = lj - xA.w;
            float dB0 = lj - xB.y, dB1 = lj - xB.w;
            float e0 = ex2f(dA0 * dA0 * EX2C);
            float e1 = ex2f(dA1 * dA1 * EX2C);
            float e8 = ex2f(dB0 * dB0 * EX2C);
            float e9 = ex2f(dB1 * dB1 * EX2C);

            int nbase = jl * 10;
#pragma unroll
            for (int c = 0; c < 10; ++c) {
                int n  = nbase + c;
                int nc = n >> 3;
                int r  = n & 7;
                uint2 z;
                if (c == 0) {
                    z.x = pack_bf16(e0, e1);
                    z.y = pack_bf16(e8, e9);
                } else if (c == 9) {
                    z.x = 0u; z.y = 0u;
                } else {
                    z.x = pack_bf16(e0 * Y0[c - 1], e1 * Y1[c - 1]);
                    z.y = pack_bf16(e8 * Y8[c - 1], e9 * Y9[c - 1]);
                }
                zk[nc * 32 + r * 4] = z;
            }
        }
    }

    // PDL: wait for prep kernel's g_Aperm writes to be visible
    cudaGridDependencySynchronize();

    GROUP_BAR(1 + ks);                // our Z half is ready

    // ===== Phase 2: mma mainloop (R13 form: chunked, 4 A frags) =====
    const int lane = tl & 31;
    const int wid  = tl >> 5;
    const int slab = wid & 3;
    const int nh   = wid >> 2;
    const int nc0  = nh * 3;
    const int ncnt = nh ? 2 : 3;

    float acc[3][4];
#pragma unroll
    for (int a = 0; a < 3; ++a)
#pragma unroll
        for (int r = 0; r < 4; ++r) acc[a][r] = 0.0f;

    const uint4* gA = (const uint4*)g_Aperm + (size_t)b * 8192 + ks * 4096
                      + slab * 32 + lane;
    const uint2* zb = sZ + (size_t)(ks * 32 * 5 + nc0) * 32 + lane;

#pragma unroll 2
    for (int ch = 0; ch < 8; ++ch) {
        uint4 af[4];
        uint2 zf[4][3];
#pragma unroll
        for (int kst = 0; kst < 4; ++kst)
            af[kst] = __ldg(gA + (ch * 4 + kst) * 128);
#pragma unroll
        for (int kst = 0; kst < 4; ++kst)
#pragma unroll
            for (int cc = 0; cc < 3; ++cc)
                if (cc < ncnt)
                    zf[kst][cc] = zb[((ch * 4 + kst) * 5 + cc) * 32];
#pragma unroll
        for (int kst = 0; kst < 4; ++kst)
#pragma unroll
            for (int cc = 0; cc < 3; ++cc)
                if (cc < ncnt)
                    MMA_BF16(acc[cc], af[kst], zf[kst][cc]);
    }

    // ===== epilogue: cross-group reduce + normalize + store =====
    __syncthreads();
    float* sD = (float*)sZ;

    if (ks == 1) {
#pragma unroll
        for (int cc = 0; cc < 3; ++cc) {
            if (cc < ncnt) {
                float4 v = make_float4(acc[cc][0], acc[cc][1], acc[cc][2], acc[cc][3]);
                *(float4*)(sD + (((nc0 + cc) * 4 + slab) * 32 + lane) * 4) = v;
            }
        }
    }
    __syncthreads();
    if (ks == 0) {
#pragma unroll
        for (int cc = 0; cc < 3; ++cc) {
            if (cc < ncnt) {
                float4* p4 = (float4*)(sD + (((nc0 + cc) * 4 + slab) * 32 + lane) * 4);
                float4 v = *p4;
                v.x += acc[cc][0]; v.y += acc[cc][1];
                v.z += acc[cc][2]; v.w += acc[cc][3];
                *p4 = v;
            }
        }
    }
    __syncthreads();

#pragma unroll
    for (int rep = 0; rep < 5; ++rep) {
        int o = t + rep * 512;
        if (o < 2304) {
            int i   = o / 36;
            int rem = o - i * 36;
            int j   = rem / 9;
            int c   = rem - j * 9;
            int sl = i >> 4, rr = i & 15, half = rr >> 3, r8 = rr & 7;
            int col  = j * 10 + c;
            int idx  = (((col >> 3) * 4 + sl) * 32 + r8 * 4 + ((col & 7) >> 1)) * 4
                       + half * 2 + (col & 1);
            int colD = j * 10;
            int idxD = (((colD >> 3) * 4 + sl) * 32 + r8 * 4 + ((colD & 7) >> 1)) * 4
                       + half * 2 + (colD & 1);
            float dens = sD[idxD];
            float v = (c == 0) ? dens : sD[idx] / (dens + 1e-6f);
            out[8192 + (size_t)(b * 4096 + i * 64 + jt * 4 + j) * 9 + c] = v;
        }
    }
}

extern "C" void kernel_launch(void* const* d_in, const int* in_sizes, int n_in,
                              void* d_out, int out_size)
{
    const float* X = (const float*)d_in[0];
    const float* Y = (const float*)d_in[1];
    float* out = (float*)d_out;

    const int zbytes = ZSLOTS * (int)sizeof(uint2);   // 81920
    cudaFuncSetAttribute(rkhs_mma_kernel,
                         cudaFuncAttributeMaxDynamicSharedMemorySize, zbytes);

    rkhs_prep_kernel<<<512, 256>>>(X, out);

    // PDL launch: overlap with prep; dependency resolved in-kernel
    cudaLaunchConfig_t cfg = {};
    cfg.gridDim  = dim3(256);
    cfg.blockDim = dim3(512);
    cfg.dynamicSmemBytes = zbytes;
    cfg.stream = 0;
    cudaLaunchAttribute attrs[1];
    attrs[0].id = cudaLaunchAttributeProgrammaticStreamSerialization;
    attrs[0].val.programmaticStreamSerializationAllowed = 1;
    cfg.attrs = attrs;
    cfg.numAttrs = 1;
    cudaLaunchKernelEx(&cfg, rkhs_mma_kernel, X, Y, out);
}